// round 2
// baseline (speedup 1.0000x reference)
#include <cuda_runtime.h>
#include <math.h>

#define BB 256
#define SS 6
#define CC 80
#define FF 2048
#define EE 300
#define HH 1024
#define PP 196

// output layout (float offsets)
#define OUT_OUTPUT 0              // [256*80]
#define OUT_PROBS  20480          // [256*6]
#define OUT_SEN    22016          // [1]
#define OUT_BEN    22017          // [1]
#define OUT_COMATS 22018          // [256*80*80]

// scratch (device globals — no allocation allowed)
__device__ float d_img[BB*FF];
__device__ int   d_ids[BB];
__device__ float d_cm[SS*CC*CC];    // updated comatrix
__device__ float d_cp[SS*CC*CC];    // comat2prob per scene
__device__ float d_adj[SS*CC*CC];   // per-scene adjacency
__device__ float d_X0[CC*HH];       // inp @ W1
__device__ float d_hs[SS*CC*HH];    // leakyrelu(adj_s @ X0)
__device__ float d_v[BB*HH];        // img_feats @ W2^T

// ---------------- K1: global max-pool over 14x14 ----------------
__global__ void k_maxpool(const float* __restrict__ x) {
    int gw = (blockIdx.x * blockDim.x + threadIdx.x) >> 5;
    int lane = threadIdx.x & 31;
    if (gw >= BB * FF) return;
    const float* p = x + (size_t)gw * PP;
    float m = -3.4e38f;
    #pragma unroll
    for (int i = 0; i < 7; i++) {
        int idx = lane + i * 32;
        if (idx < PP) m = fmaxf(m, p[idx]);
    }
    #pragma unroll
    for (int o = 16; o; o >>= 1) m = fmaxf(m, __shfl_xor_sync(0xffffffffu, m, o));
    if (lane == 0) d_img[gw] = m;
}

// ------------- K2: scene scores + softmax + argmax -------------
__global__ void k_scene(const float* __restrict__ Wsc, float* __restrict__ out) {
    int b = blockIdx.x;
    int tid = threadIdx.x;
    __shared__ float sh[6][256];
    float acc[6] = {0.f,0.f,0.f,0.f,0.f,0.f};
    const float* row = d_img + b * FF;
    for (int f = tid; f < FF; f += 256) {
        float xv = row[f];
        const float* w = Wsc + f * SS;
        #pragma unroll
        for (int s = 0; s < 6; s++) acc[s] = fmaf(xv, w[s], acc[s]);
    }
    #pragma unroll
    for (int s = 0; s < 6; s++) sh[s][tid] = acc[s];
    __syncthreads();
    for (int st = 128; st > 0; st >>= 1) {
        if (tid < st) {
            #pragma unroll
            for (int s = 0; s < 6; s++) sh[s][tid] += sh[s][tid + st];
        }
        __syncthreads();
    }
    if (tid == 0) {
        float sc[6]; float m = -3.4e38f; int am = 0;
        #pragma unroll
        for (int s = 0; s < 6; s++) {
            sc[s] = sh[s][0];
            if (sc[s] > m) { m = sc[s]; am = s; }
        }
        float e[6], sum = 0.f;
        #pragma unroll
        for (int s = 0; s < 6; s++) { e[s] = expf(sc[s] - m); sum += e[s]; }
        float inv = 1.0f / sum;
        #pragma unroll
        for (int s = 0; s < 6; s++) out[OUT_PROBS + b * 6 + s] = e[s] * inv;
        d_ids[b] = am;
    }
}

// ------------- K3: comatrix scatter update -------------
__global__ void k_comat(const float* __restrict__ y, const float* __restrict__ com_in) {
    __shared__ int sids[BB];
    int tid = threadIdx.x;
    sids[tid] = d_ids[tid];
    __syncthreads();
    int idx = blockIdx.x * 256 + tid;
    if (idx >= SS * CC * CC) return;
    int s = idx / (CC * CC);
    int r = idx - s * CC * CC;
    int i = r / CC, j = r - i * CC;
    float acc = 0.f;
    for (int b = 0; b < BB; b++) {
        if (sids[b] == s) acc += y[b * CC + i] * y[b * CC + j];
    }
    d_cm[idx] = com_in[idx] + acc;
}

// ------------- K4: comat2prob + gen_adj (per scene) -------------
__global__ void k_adj() {
    int s = blockIdx.x, tid = threadIdx.x;
    __shared__ float cp[CC * CC];
    __shared__ float dg[CC];
    __shared__ float Dv[CC];
    const float* cm = d_cm + s * CC * CC;
    for (int i = tid; i < CC; i += 256) dg[i] = cm[i * CC + i];
    __syncthreads();
    for (int idx = tid; idx < CC * CC; idx += 256) {
        int i = idx / CC, j = idx - i * CC;
        float vv = (i == j) ? 1.0f : cm[idx] / (dg[i] + 1e-8f);
        cp[idx] = vv;
        d_cp[s * CC * CC + idx] = vv;
    }
    __syncthreads();
    for (int i = tid; i < CC; i += 256) {
        float sm = 0.f;
        for (int j = 0; j < CC; j++) sm += cp[i * CC + j];
        Dv[i] = rsqrtf(sm);
    }
    __syncthreads();
    for (int idx = tid; idx < CC * CC; idx += 256) {
        int i = idx / CC, j = idx - i * CC;
        d_adj[s * CC * CC + idx] = Dv[i] * cp[j * CC + i] * Dv[j];
    }
}

// ------------- K5: gather comats to output -------------
__global__ void k_gather(float* __restrict__ out) {
    int idx = blockIdx.x * 256 + threadIdx.x;       // over B * 3200 float2
    if (idx >= BB * (CC * CC / 2)) return;
    int b = idx / (CC * CC / 2);
    int r = idx - b * (CC * CC / 2);
    int s = d_ids[b];
    const float2* src = (const float2*)(d_cp + s * CC * CC);
    ((float2*)(out + OUT_COMATS))[idx] = src[r];
}

// ------------- K6: entropy terms -------------
__global__ void k_entropy(float* __restrict__ out) {
    int b = threadIdx.x;  // 256 threads == B
    __shared__ float shE[256];
    __shared__ float shP[6][256];
    float en = 0.f;
    #pragma unroll
    for (int s = 0; s < 6; s++) {
        float p = out[OUT_PROBS + b * 6 + s];
        en -= p * logf(p + 1e-7f);
        shP[s][b] = p;
    }
    shE[b] = en;
    __syncthreads();
    for (int st = 128; st > 0; st >>= 1) {
        if (b < st) {
            shE[b] += shE[b + st];
            #pragma unroll
            for (int s = 0; s < 6; s++) shP[s][b] += shP[s][b + st];
        }
        __syncthreads();
    }
    if (b == 0) {
        out[OUT_SEN] = shE[0] / 256.0f;
        float maxen = -logf(1.0f / 6.0f + 1e-7f);
        float be = 0.f;
        #pragma unroll
        for (int s = 0; s < 6; s++) {
            float mp = shP[s][0] / 256.0f;
            be -= mp * logf(mp + 1e-7f);
        }
        out[OUT_BEN] = (maxen - be) * 100.0f;
    }
}

// ------------- K7: X0 = inp @ W1  [80,300]x[300,1024] -------------
__global__ void k_x0(const float* __restrict__ inp, const float* __restrict__ W1) {
    __shared__ float inpS[16][EE];
    int tid = threadIdx.x;
    int cg = blockIdx.x, rg = blockIdx.y;
    for (int l = tid; l < 16 * EE; l += 256) {
        int r = l / EE, c = l - r * EE;
        inpS[r][c] = inp[(rg * 16 + r) * EE + c];
    }
    __syncthreads();
    int col = cg * 128 + (tid & 127);
    int half = tid >> 7;
    float acc[8] = {};
    for (int k = 0; k < EE; k++) {
        float w = W1[k * HH + col];
        #pragma unroll
        for (int rr = 0; rr < 8; rr++)
            acc[rr] = fmaf(inpS[half + 2 * rr][k], w, acc[rr]);
    }
    #pragma unroll
    for (int rr = 0; rr < 8; rr++)
        d_X0[(rg * 16 + half + 2 * rr) * HH + col] = acc[rr];
}

// ------------- K8: h_s = leakyrelu(adj_s @ X0) (6 scenes) -------------
__global__ void k_h() {
    int s = blockIdx.x;   // 0..5
    int g = blockIdx.y;   // 0..15  (cols g*64 .. g*64+63)
    __shared__ float adjS[CC * CC];   // 25.6 KB
    __shared__ float xS[CC][64];      // 20.5 KB
    int tid = threadIdx.x;
    for (int i = tid; i < CC * CC; i += 256) adjS[i] = d_adj[s * CC * CC + i];
    for (int i = tid; i < CC * 64; i += 256) {
        int r = i >> 6, c = i & 63;
        xS[r][c] = d_X0[r * HH + g * 64 + c];
    }
    __syncthreads();
    int col = tid & 63;
    int r0 = tid >> 6;   // 0..3
    float acc[20];
    #pragma unroll
    for (int a = 0; a < 20; a++) acc[a] = 0.f;
    for (int k = 0; k < CC; k++) {
        float xv = xS[k][col];
        #pragma unroll
        for (int a = 0; a < 20; a++)
            acc[a] = fmaf(adjS[(r0 + 4 * a) * CC + k], xv, acc[a]);
    }
    #pragma unroll
    for (int a = 0; a < 20; a++) {
        int row = r0 + 4 * a;
        float hv = acc[a];
        hv = hv > 0.f ? hv : 0.2f * hv;
        d_hs[(s * CC + row) * HH + g * 64 + col] = hv;
    }
}

// ------------- K9: v = img_feats @ W2^T  (NT GEMM, M=256,N=1024,K=2048) -------------
__global__ void k_vgemm(const float* __restrict__ W2) {
    __shared__ float As[32][34];   // k-major, padded
    __shared__ float Bs[32][68];   // k-major, padded (16B-aligned rows)
    int tid = threadIdx.x;
    int row0 = blockIdx.y * 32;
    int col0 = blockIdx.x * 64;
    int ty = tid >> 4;   // 0..15 -> 2 rows each
    int tx = tid & 15;   // 0..15 -> 4 cols each
    float acc[2][4] = {};
    const float* Abase = d_img + (size_t)row0 * FF;
    const float* Bbase = W2 + (size_t)col0 * FF;
    for (int k0 = 0; k0 < FF; k0 += 32) {
        int l = tid;
        #pragma unroll
        for (int it = 0; it < 4; it++) {   // 32x32 A tile
            int r = l >> 5, c = l & 31;
            As[c][r] = Abase[r * FF + k0 + c];
            l += 256;
        }
        l = tid;
        #pragma unroll
        for (int it = 0; it < 8; it++) {   // 64x32 B tile
            int r = l >> 5, c = l & 31;
            Bs[c][r] = Bbase[r * FF + k0 + c];
            l += 256;
        }
        __syncthreads();
        #pragma unroll
        for (int kk = 0; kk < 32; kk++) {
            float2 a = *(const float2*)&As[kk][ty * 2];
            float4 bb = *(const float4*)&Bs[kk][tx * 4];
            acc[0][0] = fmaf(a.x, bb.x, acc[0][0]);
            acc[0][1] = fmaf(a.x, bb.y, acc[0][1]);
            acc[0][2] = fmaf(a.x, bb.z, acc[0][2]);
            acc[0][3] = fmaf(a.x, bb.w, acc[0][3]);
            acc[1][0] = fmaf(a.y, bb.x, acc[1][0]);
            acc[1][1] = fmaf(a.y, bb.y, acc[1][1]);
            acc[1][2] = fmaf(a.y, bb.z, acc[1][2]);
            acc[1][3] = fmaf(a.y, bb.w, acc[1][3]);
        }
        __syncthreads();
    }
    #pragma unroll
    for (int i = 0; i < 2; i++) {
        int r = row0 + ty * 2 + i;
        #pragma unroll
        for (int j = 0; j < 4; j++)
            d_v[r * HH + col0 + tx * 4 + j] = acc[i][j];
    }
}

// ------------- K10: g = h_s · v[b];  output[b] = adj_s @ g -------------
__global__ void k_out(float* __restrict__ out) {
    int b = blockIdx.x;
    int tid = threadIdx.x;
    int lane = tid & 31, w = tid >> 5;
    __shared__ float vb[HH];
    __shared__ float g[CC];
    int s = d_ids[b];
    for (int i = tid; i < HH; i += 256) vb[i] = d_v[b * HH + i];
    __syncthreads();
    for (int j = w; j < CC; j += 8) {
        const float* hr = d_hs + (size_t)(s * CC + j) * HH;
        float acc = 0.f;
        for (int k = lane; k < HH; k += 32) acc = fmaf(hr[k], vb[k], acc);
        #pragma unroll
        for (int o = 16; o; o >>= 1) acc += __shfl_xor_sync(0xffffffffu, acc, o);
        if (lane == 0) g[j] = acc;
    }
    __syncthreads();
    if (tid < CC) {
        const float* ar = d_adj + s * CC * CC + tid * CC;
        float acc = 0.f;
        #pragma unroll 8
        for (int j = 0; j < CC; j++) acc = fmaf(ar[j], g[j], acc);
        out[OUT_OUTPUT + b * CC + tid] = acc;
    }
}

extern "C" void kernel_launch(void* const* d_in, const int* in_sizes, int n_in,
                              void* d_out, int out_size) {
    const float* x    = (const float*)d_in[0];
    const float* inp  = (const float*)d_in[1];
    const float* y    = (const float*)d_in[2];
    const float* com  = (const float*)d_in[3];
    const float* Wsc  = (const float*)d_in[4];
    const float* W1   = (const float*)d_in[5];
    const float* W2   = (const float*)d_in[6];
    float* out = (float*)d_out;

    k_maxpool<<<(BB * FF) / 8, 256>>>(x);                 // d_img
    k_x0<<<dim3(8, 5), 256>>>(inp, W1);                   // d_X0 (input-only dep)
    k_scene<<<BB, 256>>>(Wsc, out);                       // probs + ids
    k_comat<<<(SS * CC * CC + 255) / 256, 256>>>(y, com); // d_cm
    k_adj<<<SS, 256>>>();                                 // d_cp, d_adj
    k_h<<<dim3(6, 16), 256>>>();                          // d_hs
    k_vgemm<<<dim3(16, 8), 256>>>(W2);                    // d_v
    k_gather<<<(BB * (CC * CC / 2) + 255) / 256, 256>>>(out); // comats out
    k_entropy<<<1, 256>>>(out);                           // scalars
    k_out<<<BB, 256>>>(out);                              // output
}